// round 16
// baseline (speedup 1.0000x reference)
#include <cuda_runtime.h>
#include <cuda_bf16.h>
#include <cstdint>

#define NN   50000
#define EE   800000
#define HH   64
#define EAD  16
#define LLAY 5
#define GG   512
#define IN2  80
#define FD   320   // L*H
#define NBLK 49    // ceil(NN/1024)
#define NBM  782   // ceil(NN/64)
#define SP   72    // smem k-stride (bf16) for 64-wide tiles
#define ECHK 128   // edges per kAggM chunk
#define EST  20    // bf16 k-stride for ea tiles
#define MWS  72    // float stride of mw rows

typedef unsigned long long ull;

// ---------------- device scratch ----------------
__device__ int   g_flag64;
__device__ int   g_cnt[NN];
__device__ int   g_off[NN + 1];
__device__ int   g_cur[NN];
__device__ int   g_bsum[NBLK];
__device__ int   g_srcS[EE];
__device__ __align__(16) unsigned g_eaH[(size_t)EE * 8];   // ea sorted by dst, bf16-hi packed
__device__ __align__(16) unsigned g_eaL[(size_t)EE * 8];   // bf16-lo packed
__device__ __align__(16) float g_t1[(size_t)NN * HH];
__device__ __align__(16) float g_agg[(size_t)NN * HH];
__device__ __align__(16) float g_xA[(size_t)NN * HH];
__device__ __align__(16) float g_xB[(size_t)NN * HH];
__device__ float g_pool[(size_t)GG * FD];
__device__ __align__(16) __nv_bfloat16 g_wB[20][2][64][SP];
__device__ __align__(16) __nv_bfloat16 g_wE[LLAY][2][64][EST];
__device__ __align__(16) __nv_bfloat16 g_wT[2][64][SP];

__device__ __forceinline__ int loadIdx(const void* p, long long i, int is64) {
    if (is64) return (int)((const long long*)p)[i];
    return ((const int*)p)[i];
}
__device__ __forceinline__ const float* pickIn(int sel, const float* xin) {
    switch (sel) { case 2: return g_xA; case 3: return g_xB; default: return xin; }
}
__device__ __forceinline__ float* pickOut(int sel) { return (sel == 2) ? g_xA : g_xB; }

// ---------------- bf16 pack helpers ----------------
__device__ __forceinline__ unsigned pbHi(float x, float y) {
    __nv_bfloat16 hx = __float2bfloat16(x), hy = __float2bfloat16(y);
    return (unsigned)__bfloat16_as_ushort(hx) | ((unsigned)__bfloat16_as_ushort(hy) << 16);
}
__device__ __forceinline__ unsigned pbLo(float x, float y) {
    __nv_bfloat16 hx = __float2bfloat16(x), hy = __float2bfloat16(y);
    float lx = x - __bfloat162float(hx), ly = y - __bfloat162float(hy);
    __nv_bfloat16 bx = __float2bfloat16(lx), by = __float2bfloat16(ly);
    return (unsigned)__bfloat16_as_ushort(bx) | ((unsigned)__bfloat16_as_ushort(by) << 16);
}

// ---------------- mma.sync m16n8k16 bf16 ----------------
__device__ __forceinline__ void mma16816(float* c, unsigned a0, unsigned a1,
                                         unsigned a2, unsigned a3,
                                         unsigned b0, unsigned b1) {
    asm volatile(
        "mma.sync.aligned.m16n8k16.row.col.f32.bf16.bf16.f32 "
        "{%0,%1,%2,%3}, {%4,%5,%6,%7}, {%8,%9}, {%0,%1,%2,%3};"
        : "+f"(c[0]), "+f"(c[1]), "+f"(c[2]), "+f"(c[3])
        : "r"(a0), "r"(a1), "r"(a2), "r"(a3), "r"(b0), "r"(b1));
}

// ---------------- setup ----------------
__global__ void kDetect(const void* ei) {
    const int* p = (const int*)ei;
    g_flag64 = (p[1] == 0 && p[3] == 0 && p[5] == 0 && p[7] == 0) ? 1 : 0;
}
__global__ void kZero() {
    int i = blockIdx.x * blockDim.x + threadIdx.x;
    if (i < NN) g_cnt[i] = 0;
    if (i < GG * FD) g_pool[i] = 0.f;
}
__global__ void kCount(const void* __restrict__ ei) {
    int e = blockIdx.x * blockDim.x + threadIdx.x;
    if (e >= EE) return;
    int f = g_flag64;
    int s = loadIdx(ei, e, f);
    int d = loadIdx(ei, (long long)EE + e, f);
    if (s != d) atomicAdd(&g_cnt[d], 1);
}
__global__ void kScanA() {
    __shared__ int wsum[32];
    int tid = threadIdx.x, lane = tid & 31, wid = tid >> 5;
    int i = blockIdx.x * 1024 + tid;
    int v = (i < NN) ? g_cnt[i] : 0;
    int x = v;
#pragma unroll
    for (int o = 1; o < 32; o <<= 1) {
        int t = __shfl_up_sync(0xffffffffu, x, o);
        if (lane >= o) x += t;
    }
    if (lane == 31) wsum[wid] = x;
    __syncthreads();
    if (tid < 32) {
        int y = wsum[tid];
#pragma unroll
        for (int o = 1; o < 32; o <<= 1) {
            int t = __shfl_up_sync(0xffffffffu, y, o);
            if (tid >= o) y += t;
        }
        wsum[tid] = y;
    }
    __syncthreads();
    int incl = x + (wid ? wsum[wid - 1] : 0);
    if (i < NN) g_off[i] = incl - v;
    if (tid == 1023) g_bsum[blockIdx.x] = incl;
}
__global__ void kScanB() {
    if (threadIdx.x == 0) {
        int s = 0;
        for (int b = 0; b < NBLK; b++) { int t = g_bsum[b]; g_bsum[b] = s; s += t; }
        g_off[NN] = s;
    }
}
__global__ void kScanC() {
    int i = blockIdx.x * 1024 + threadIdx.x;
    if (i < NN) {
        int v = g_off[i] + g_bsum[blockIdx.x];
        g_off[i] = v;
        g_cur[i] = v;
    }
}
// scatter: convert ea -> bf16 hi/lo ONCE, store in dst-sorted order
__global__ void kScatter(const void* __restrict__ ei, const float* __restrict__ ea) {
    int e = blockIdx.x * blockDim.x + threadIdx.x;
    if (e >= EE) return;
    int f = g_flag64;
    int s = loadIdx(ei, e, f);
    int d = loadIdx(ei, (long long)EE + e, f);
    if (s == d) return;
    int pos = atomicAdd(&g_cur[d], 1);
    g_srcS[pos] = s;
    const float4* s4 = (const float4*)(ea + (size_t)e * EAD);
    uint4 h0, h1, l0, l1;
    {
        float4 v0 = s4[0], v1 = s4[1], v2 = s4[2], v3 = s4[3];
        h0.x = pbHi(v0.x, v0.y); h0.y = pbHi(v0.z, v0.w);
        h0.z = pbHi(v1.x, v1.y); h0.w = pbHi(v1.z, v1.w);
        h1.x = pbHi(v2.x, v2.y); h1.y = pbHi(v2.z, v2.w);
        h1.z = pbHi(v3.x, v3.y); h1.w = pbHi(v3.z, v3.w);
        l0.x = pbLo(v0.x, v0.y); l0.y = pbLo(v0.z, v0.w);
        l0.z = pbLo(v1.x, v1.y); l0.w = pbLo(v1.z, v1.w);
        l1.x = pbLo(v2.x, v2.y); l1.y = pbLo(v2.z, v2.w);
        l1.z = pbLo(v3.x, v3.y); l1.w = pbLo(v3.z, v3.w);
    }
    ((uint4*)g_eaH)[(size_t)pos * 2]     = h0;
    ((uint4*)g_eaH)[(size_t)pos * 2 + 1] = h1;
    ((uint4*)g_eaL)[(size_t)pos * 2]     = l0;
    ((uint4*)g_eaL)[(size_t)pos * 2 + 1] = l1;
}

// ---------------- weight packing ----------------
__global__ void kPackW(const float* __restrict__ n2w1, const float* __restrict__ n2w2,
                       const float* __restrict__ n1w1, const float* __restrict__ n1w2) {
    int idx = blockIdx.x * 256 + threadIdx.x;
    if (idx >= 20 * 4096) return;
    int m = idx / 4096;
    int e = idx % 4096;
    int k = e >> 6, c = e & 63;
    int l = m >> 2, s = m & 3;
    float v;
    if (s == 0)      v = n2w2[((size_t)l * 64 + k) * 64 + c];
    else if (s == 1) v = n1w1[((size_t)l * 64 + k) * 64 + c];
    else if (s == 2) v = n1w2[((size_t)l * 64 + k) * 64 + c];
    else             v = (l < 4) ? n2w1[((size_t)(l + 1) * 80 + k) * 64 + c] : 0.f;
    __nv_bfloat16 hi = __float2bfloat16(v);
    __nv_bfloat16 lo = __float2bfloat16(v - __bfloat162float(hi));
    g_wB[m][0][c][k] = hi;
    g_wB[m][1][c][k] = lo;
}
__global__ void kPackE(const float* __restrict__ n2w1) {
    int idx = blockIdx.x * 256 + threadIdx.x;
    if (idx < LLAY * 1024) {
        int l = idx >> 10, e = idx & 1023;
        int k = e >> 6, c = e & 63;
        float v = n2w1[((size_t)l * IN2 + 64 + k) * HH + c];
        __nv_bfloat16 hi = __float2bfloat16(v);
        __nv_bfloat16 lo = __float2bfloat16(v - __bfloat162float(hi));
        g_wE[l][0][c][k] = hi;
        g_wE[l][1][c][k] = lo;
    } else if (idx < LLAY * 1024 + 4096) {
        int e = idx - LLAY * 1024;
        int k = e >> 6, c = e & 63;
        float v = n2w1[(size_t)k * HH + c];
        __nv_bfloat16 hi = __float2bfloat16(v);
        __nv_bfloat16 lo = __float2bfloat16(v - __bfloat162float(hi));
        g_wT[0][c][k] = hi;
        g_wT[1][c][k] = lo;
    }
}

// ---------------- kT1M: t1 = x @ W1a(l0) + b1, 256 threads / 8 warps ----------------
__global__ __launch_bounds__(256) void kT1M(const float* __restrict__ X,
                                            const float* __restrict__ B) {
    __shared__ __align__(16) __nv_bfloat16 sAhi[64][SP];
    __shared__ __align__(16) __nv_bfloat16 sAlo[64][SP];
    __shared__ __align__(16) __nv_bfloat16 sWhi[64][SP];
    __shared__ __align__(16) __nv_bfloat16 sWlo[64][SP];
    __shared__ float sB[64];
    int tid = threadIdx.x, lane = tid & 31, warp = tid >> 5;
    int g8 = lane >> 2, tg = lane & 3;
    int eg = warp >> 1, nh = warp & 1;
    int base = blockIdx.x * 64;
    if (tid < 64) sB[tid] = B[tid];
    for (int i = tid; i < 1024; i += 256) {
        int r = i >> 4, cc = (i & 15) << 2;
        int gr = base + r;
        float4 v = (gr < NN) ? *(const float4*)&X[(size_t)gr * HH + cc]
                             : make_float4(0.f, 0.f, 0.f, 0.f);
        *(unsigned*)&sAhi[r][cc]     = pbHi(v.x, v.y);
        *(unsigned*)&sAhi[r][cc + 2] = pbHi(v.z, v.w);
        *(unsigned*)&sAlo[r][cc]     = pbLo(v.x, v.y);
        *(unsigned*)&sAlo[r][cc + 2] = pbLo(v.z, v.w);
    }
    {
        const float4* sH = (const float4*)&g_wT[0][0][0];
        const float4* sL = (const float4*)&g_wT[1][0][0];
        float4* dH = (float4*)&sWhi[0][0];
        float4* dL = (float4*)&sWlo[0][0];
        for (int i = tid; i < 576; i += 256) { dH[i] = sH[i]; dL[i] = sL[i]; }
    }
    __syncthreads();
    int lr0 = eg * 16 + g8, lr1 = lr0 + 8;
    float acc[4][4];
#pragma unroll
    for (int nt = 0; nt < 4; nt++)
#pragma unroll
        for (int j = 0; j < 4; j++) acc[nt][j] = 0.f;
#pragma unroll
    for (int k = 0; k < 4; k++) {
        int k0 = k * 16 + tg * 2;
        unsigned ah0 = *(const unsigned*)&sAhi[lr0][k0];
        unsigned ah1 = *(const unsigned*)&sAhi[lr1][k0];
        unsigned ah2 = *(const unsigned*)&sAhi[lr0][k0 + 8];
        unsigned ah3 = *(const unsigned*)&sAhi[lr1][k0 + 8];
        unsigned al0 = *(const unsigned*)&sAlo[lr0][k0];
        unsigned al1 = *(const unsigned*)&sAlo[lr1][k0];
        unsigned al2 = *(const unsigned*)&sAlo[lr0][k0 + 8];
        unsigned al3 = *(const unsigned*)&sAlo[lr1][k0 + 8];
#pragma unroll
        for (int nt = 0; nt < 4; nt++) {
            int nr = nh * 32 + nt * 8 + g8;
            unsigned bh0 = *(const unsigned*)&sWhi[nr][k0];
            unsigned bh1 = *(const unsigned*)&sWhi[nr][k0 + 8];
            unsigned bl0 = *(const unsigned*)&sWlo[nr][k0];
            unsigned bl1 = *(const unsigned*)&sWlo[nr][k0 + 8];
            mma16816(acc[nt], ah0, ah1, ah2, ah3, bh0, bh1);
            mma16816(acc[nt], ah0, ah1, ah2, ah3, bl0, bl1);
            mma16816(acc[nt], al0, al1, al2, al3, bh0, bh1);
        }
    }
    int r0 = base + lr0, r1 = base + lr1;
#pragma unroll
    for (int nt = 0; nt < 4; nt++) {
        int col0 = nh * 32 + nt * 8 + tg * 2;
        if (r0 < NN)
            *(float2*)&g_t1[(size_t)r0 * HH + col0] =
                make_float2(acc[nt][0] + sB[col0], acc[nt][1] + sB[col0 + 1]);
        if (r1 < NN)
            *(float2*)&g_t1[(size_t)r1 * HH + col0] =
                make_float2(acc[nt][2] + sB[col0], acc[nt][3] + sB[col0 + 1]);
    }
}

// ---------------- kAggM: 8 nodes/block, 1 node/warp, pre-converted ea ----------------
__global__ __launch_bounds__(256) void kAggM(int layer) {
    __shared__ __align__(16) char uni[ECHK * MWS * 4];   // (seaH|seaL) ∪ mw
    __shared__ __align__(16) __nv_bfloat16 sWh[64][EST];
    __shared__ __align__(16) __nv_bfloat16 sWl[64][EST];
    __shared__ int ssrc[ECHK];
    __nv_bfloat16* seaH = (__nv_bfloat16*)uni;
    __nv_bfloat16* seaL = seaH + ECHK * EST;
    float* mw = (float*)uni;

    int tid = threadIdx.x, lane = tid & 31, warp = tid >> 5;
    int g8 = lane >> 2, tg = lane & 3;

    for (int i = tid; i < 1024; i += 256) {
        int c = i >> 4, k = i & 15;
        sWh[c][k] = g_wE[layer][0][c][k];
        sWl[c][k] = g_wE[layer][1][c][k];
    }

    int nb = blockIdx.x * 8;
    int n = nb + warp;
    int beg = g_off[n], end = g_off[n + 1];
    int bBeg = g_off[nb], bEnd = g_off[nb + 8];
    float accA = 0.f, accB = 0.f;

    for (int cb = bBeg; cb < bEnd; cb += ECHK) {
        int cnt = min(ECHK, bEnd - cb);
        __syncthreads();
        // pure-copy staging: ea already bf16 hi/lo packed
        for (int i = tid; i < cnt * 8; i += 256) {
            int q = i >> 3, w = i & 7;
            *(unsigned*)&seaH[q * EST + 2 * w] = g_eaH[(size_t)(cb + q) * 8 + w];
            *(unsigned*)&seaL[q * EST + 2 * w] = g_eaL[(size_t)(cb + q) * 8 + w];
        }
        for (int i = tid; i < cnt; i += 256) ssrc[i] = g_srcS[cb + i];
        __syncthreads();

        float d[8][4];
#pragma unroll
        for (int nt = 0; nt < 8; nt++)
#pragma unroll
            for (int j = 0; j < 4; j++) d[nt][j] = 0.f;
        {
            int er0 = warp * 16 + g8;
            int k0 = tg * 2;
            unsigned ah0 = *(const unsigned*)&seaH[er0 * EST + k0];
            unsigned ah1 = *(const unsigned*)&seaH[(er0 + 8) * EST + k0];
            unsigned ah2 = *(const unsigned*)&seaH[er0 * EST + k0 + 8];
            unsigned ah3 = *(const unsigned*)&seaH[(er0 + 8) * EST + k0 + 8];
            unsigned al0 = *(const unsigned*)&seaL[er0 * EST + k0];
            unsigned al1 = *(const unsigned*)&seaL[(er0 + 8) * EST + k0];
            unsigned al2 = *(const unsigned*)&seaL[er0 * EST + k0 + 8];
            unsigned al3 = *(const unsigned*)&seaL[(er0 + 8) * EST + k0 + 8];
#pragma unroll
            for (int nt = 0; nt < 8; nt++) {
                int nr = nt * 8 + g8;
                unsigned bh0 = *(const unsigned*)&sWh[nr][k0];
                unsigned bh1 = *(const unsigned*)&sWh[nr][k0 + 8];
                unsigned bl0 = *(const unsigned*)&sWl[nr][k0];
                unsigned bl1 = *(const unsigned*)&sWl[nr][k0 + 8];
                mma16816(d[nt], ah0, ah1, ah2, ah3, bh0, bh1);
                mma16816(d[nt], ah0, ah1, ah2, ah3, bl0, bl1);
                mma16816(d[nt], al0, al1, al2, al3, bh0, bh1);
            }
        }
        __syncthreads();
        {
            int er0 = warp * 16 + g8;
#pragma unroll
            for (int nt = 0; nt < 8; nt++) {
                int c0 = nt * 8 + tg * 2;
                *(float2*)&mw[er0 * MWS + c0]       = make_float2(d[nt][0], d[nt][1]);
                *(float2*)&mw[(er0 + 8) * MWS + c0] = make_float2(d[nt][2], d[nt][3]);
            }
        }
        __syncthreads();

        int myB = max(beg, cb), myE = min(end, cb + cnt);
        int m = myE - myB;
        if (m > 0) {
            int q0 = myB - cb;
            float ga0, gb0, ga1 = 0.f, gb1 = 0.f, ga2 = 0.f, gb2 = 0.f;
            { int s = ssrc[q0];
              ga0 = g_t1[(size_t)s * HH + lane]; gb0 = g_t1[(size_t)s * HH + lane + 32]; }
            if (m > 1) { int s = ssrc[q0 + 1];
              ga1 = g_t1[(size_t)s * HH + lane]; gb1 = g_t1[(size_t)s * HH + lane + 32]; }
            if (m > 2) { int s = ssrc[q0 + 2];
              ga2 = g_t1[(size_t)s * HH + lane]; gb2 = g_t1[(size_t)s * HH + lane + 32]; }
            for (int q = 0; q < m; q++) {
                float nga = 0.f, ngb = 0.f;
                if (q + 3 < m) {
                    int s = ssrc[q0 + q + 3];
                    nga = g_t1[(size_t)s * HH + lane];
                    ngb = g_t1[(size_t)s * HH + lane + 32];
                }
                float m0 = mw[(q0 + q) * MWS + lane];
                float m1 = mw[(q0 + q) * MWS + lane + 32];
                accA += fmaxf(ga0 + m0, 0.f);
                accB += fmaxf(gb0 + m1, 0.f);
                ga0 = ga1; gb0 = gb1; ga1 = ga2; gb1 = gb2; ga2 = nga; gb2 = ngb;
            }
        }
    }
    g_agg[(size_t)n * HH + lane] = accA;
    g_agg[(size_t)n * HH + lane + 32] = accB;
}

// ---------------- kNodeM: fused node update, 256 threads / 8 warps ----------------
__global__ __launch_bounds__(256) void kNodeM(int xSel, const float* __restrict__ xExt,
                                              int xOutSel,
                                              const float* __restrict__ b2,
                                              const float* __restrict__ c1,
                                              const float* __restrict__ c2,
                                              const float* __restrict__ b1n,
                                              const float* __restrict__ epsPtr,
                                              const void* __restrict__ batch, int layer) {
    __shared__ __align__(16) __nv_bfloat16 sAhi[64][SP];
    __shared__ __align__(16) __nv_bfloat16 sAlo[64][SP];
    __shared__ __align__(16) __nv_bfloat16 sWhi[64][SP];
    __shared__ __align__(16) __nv_bfloat16 sWlo[64][SP];
    __shared__ float sBias[4][64];

    int tid = threadIdx.x, lane = tid & 31, warp = tid >> 5;
    int g8 = lane >> 2, tg = lane & 3;
    int eg = warp >> 1, nh = warp & 1;
    int base = blockIdx.x * 64;
    const float* X = pickIn(xSel, xExt);
    float* Xo = pickOut(xOutSel);
    int nStages = (layer < LLAY - 1) ? 4 : 3;
    bool writeX = (layer < LLAY - 1);
    int f64 = g_flag64;

    if (tid < 64) {
        sBias[0][tid] = b2[tid];
        sBias[1][tid] = c1[tid];
        sBias[2][tid] = c2[tid];
        sBias[3][tid] = b1n ? b1n[tid] : 0.f;
    }
    for (int i = tid; i < 1024; i += 256) {
        int r = i >> 4, cc = (i & 15) << 2;
        int gr = base + r;
        float4 v = (gr < NN) ? *(const float4*)&g_agg[(size_t)gr * HH + cc]
                             : make_float4(0.f, 0.f, 0.f, 0.f);
        *(unsigned*)&sAhi[r][cc]     = pbHi(v.x, v.y);
        *(unsigned*)&sAhi[r][cc + 2] = pbHi(v.z, v.w);
        *(unsigned*)&sAlo[r][cc]     = pbLo(v.x, v.y);
        *(unsigned*)&sAlo[r][cc + 2] = pbLo(v.z, v.w);
    }
    {
        const float4* sH = (const float4*)&g_wB[layer * 4][0][0][0];
        const float4* sL = (const float4*)&g_wB[layer * 4][1][0][0];
        float4* dH = (float4*)&sWhi[0][0];
        float4* dL = (float4*)&sWlo[0][0];
        for (int i = tid; i < 576; i += 256) { dH[i] = sH[i]; dL[i] = sL[i]; }
    }

    int lr0 = eg * 16 + g8, lr1 = lr0 + 8;
    int r0 = base + lr0, r1 = base + lr1;
    bool valid0 = r0 < NN, valid1 = r1 < NN;
    float ope = 1.f + epsPtr[0];
    float cnt0 = valid0 ? (float)g_cnt[r0] : 0.f;
    float cnt1 = valid1 ? (float)g_cnt[r1] : 0.f;
    int gb0 = valid0 ? loadIdx(batch, r0, f64) : 0;
    int gb1 = valid1 ? loadIdx(batch, r1, f64) : 0;

    for (int s = 0; s < nStages; s++) {
        __syncthreads();
        float acc[4][4];
#pragma unroll
        for (int nt = 0; nt < 4; nt++)
#pragma unroll
            for (int j = 0; j < 4; j++) acc[nt][j] = 0.f;

#pragma unroll
        for (int k = 0; k < 4; k++) {
            int k0 = k * 16 + tg * 2;
            unsigned ah0 = *(const unsigned*)&sAhi[lr0][k0];
            unsigned ah1 = *(const unsigned*)&sAhi[lr1][k0];
            unsigned ah2 = *(const unsigned*)&sAhi[lr0][k0 + 8];
            unsigned ah3 = *(const unsigned*)&sAhi[lr1][k0 + 8];
            unsigned al0 = *(const unsigned*)&sAlo[lr0][k0];
            unsigned al1 = *(const unsigned*)&sAlo[lr1][k0];
            unsigned al2 = *(const unsigned*)&sAlo[lr0][k0 + 8];
            unsigned al3 = *(const unsigned*)&sAlo[lr1][k0 + 8];
#pragma unroll
            for (int nt = 0; nt < 4; nt++) {
                int nr = nh * 32 + nt * 8 + g8;
                unsigned bh0 = *(const unsigned*)&sWhi[nr][k0];
                unsigned bh1 = *(const unsigned*)&sWhi[nr][k0 + 8];
                unsigned bl0 = *(const unsigned*)&sWlo[nr][k0];
                unsigned bl1 = *(const unsigned*)&sWlo[nr][k0 + 8];
                mma16816(acc[nt], ah0, ah1, ah2, ah3, bh0, bh1);
                mma16816(acc[nt], ah0, ah1, ah2, ah3, bl0, bl1);
                mma16816(acc[nt], al0, al1, al2, al3, bh0, bh1);
            }
        }
        __syncthreads();

        if (s + 1 < nStages) {
            const float4* sH = (const float4*)&g_wB[layer * 4 + s + 1][0][0][0];
            const float4* sL = (const float4*)&g_wB[layer * 4 + s + 1][1][0][0];
            float4* dH = (float4*)&sWhi[0][0];
            float4* dL = (float4*)&sWlo[0][0];
            for (int i = tid; i < 576; i += 256) { dH[i] = sH[i]; dL[i] = sL[i]; }
        }

        bool last = (s == nStages - 1);
#pragma unroll
        for (int nt = 0; nt < 4; nt++) {
            int col0 = nh * 32 + nt * 8 + tg * 2;
            float v00, v01, v10, v11;
            if (s == 0) {
                float2 x0 = valid0 ? *(const float2*)&X[(size_t)r0 * HH + col0]
                                   : make_float2(0.f, 0.f);
                float2 x1 = valid1 ? *(const float2*)&X[(size_t)r1 * HH + col0]
                                   : make_float2(0.f, 0.f);
                v00 = acc[nt][0] + ope * x0.x + cnt0 * sBias[0][col0];
                v01 = acc[nt][1] + ope * x0.y + cnt0 * sBias[0][col0 + 1];
                v10 = acc[nt][2] + ope * x1.x + cnt1 * sBias[0][col0];
                v11 = acc[nt][3] + ope * x1.y + cnt1 * sBias[0][col0 + 1];
            } else if (s == 1) {
                v00 = fmaxf(acc[nt][0] + sBias[1][col0], 0.f);
                v01 = fmaxf(acc[nt][1] + sBias[1][col0 + 1], 0.f);
                v10 = fmaxf(acc[nt][2] + sBias[1][col0], 0.f);
                v11 = fmaxf(acc[nt][3] + sBias[1][col0 + 1], 0.f);
            } else if (s == 2) {
                v00 = acc[nt][0] + sBias[2][col0];
                v01 = acc[nt][1] + sBias[2][col0 + 1];
                v10 = acc[nt][2] + sBias[2][col0];
                v11 = acc[nt][3] + sBias[2][col0 + 1];
                if (valid0) {
                    if (writeX) *(float2*)&Xo[(size_t)r0 * HH + col0] = make_float2(v00, v01);
                    atomicAdd(&g_pool[(size_t)gb0 * FD + layer * HH + col0], v00);
                    atomicAdd(&g_pool[(size_t)gb0 * FD + layer * HH + col0 + 1], v01);
                }
                if (valid1) {
                    if (writeX) *(float2*)&Xo[(size_t)r1 * HH + col0] = make_float2(v10, v11);
                    atomicAdd(&g_pool[(size_t)gb1 * FD + layer * HH + col0], v10);
                    atomicAdd(&g_pool[(size_t)gb1 * FD + layer * HH + col0 + 1], v11);
                }
            } else {
                v00 = acc[nt][0] + sBias[3][col0];
                v01 = acc[nt][1] + sBias[3][col0 + 1];
                v10 = acc[nt][2] + sBias[3][col0];
                v11 = acc[nt][3] + sBias[3][col0 + 1];
                if (valid0) *(float2*)&g_t1[(size_t)r0 * HH + col0] = make_float2(v00, v01);
                if (valid1) *(float2*)&g_t1[(size_t)r1 * HH + col0] = make_float2(v10, v11);
            }
            if (!last) {
                *(unsigned*)&sAhi[lr0][col0] = pbHi(v00, v01);
                *(unsigned*)&sAlo[lr0][col0] = pbLo(v00, v01);
                *(unsigned*)&sAhi[lr1][col0] = pbHi(v10, v11);
                *(unsigned*)&sAlo[lr1][col0] = pbLo(v10, v11);
            }
        }
    }
}

// ---------------- final MLP ----------------
__global__ __launch_bounds__(320) void kFinal(const float* __restrict__ fw1,
                                              const float* __restrict__ fb1,
                                              const float* __restrict__ fw2,
                                              const float* __restrict__ fb2,
                                              float* __restrict__ out) {
    __shared__ float fsh[8][FD];
    __shared__ float hsh[8][FD];
    int tid = threadIdx.x;
    int gbase = blockIdx.x * 8;
    for (int i = tid; i < 8 * FD; i += 320) {
        int gg = i / FD, k = i % FD;
        fsh[gg][k] = g_pool[(size_t)(gbase + gg) * FD + k];
    }
    __syncthreads();
    float acc[8] = {0, 0, 0, 0, 0, 0, 0, 0};
    for (int k = 0; k < FD; k++) {
        float w = fw1[(size_t)k * FD + tid];
#pragma unroll
        for (int gg = 0; gg < 8; gg++) acc[gg] = fmaf(fsh[gg][k], w, acc[gg]);
    }
    float b = fb1[tid];
#pragma unroll
    for (int gg = 0; gg < 8; gg++) hsh[gg][tid] = fmaxf(acc[gg] + b, 0.f);
    __syncthreads();
    int warp = tid >> 5, lane = tid & 31;
    if (warp < 8) {
        float s = 0.f;
        for (int k = lane; k < FD; k += 32) s += hsh[warp][k] * fw2[k];
#pragma unroll
        for (int o = 16; o; o >>= 1) s += __shfl_down_sync(0xffffffffu, s, o);
        if (lane == 0) out[gbase + warp] = s + fb2[0];
    }
}

// ---------------- launch ----------------
extern "C" void kernel_launch(void* const* d_in, const int* in_sizes, int n_in,
                              void* d_out, int out_size) {
    const float* x    = (const float*)d_in[0];
    const void*  ei   = d_in[1];
    const float* ea   = (const float*)d_in[2];
    const void*  bat  = d_in[3];
    const float* n2w1 = (const float*)d_in[4];
    const float* n2b1 = (const float*)d_in[5];
    const float* n2w2 = (const float*)d_in[6];
    const float* n2b2 = (const float*)d_in[7];
    const float* n1w1 = (const float*)d_in[8];
    const float* n1b1 = (const float*)d_in[9];
    const float* n1w2 = (const float*)d_in[10];
    const float* n1b2 = (const float*)d_in[11];
    const float* fw1  = (const float*)d_in[12];
    const float* fb1  = (const float*)d_in[13];
    const float* fw2  = (const float*)d_in[14];
    const float* fb2  = (const float*)d_in[15];
    const float* eps  = (const float*)d_in[16];

    kDetect<<<1, 1>>>(ei);
    kZero<<<(GG * FD + 255) / 256, 256>>>();
    kPackE<<<(LLAY * 1024 + 4096 + 255) / 256, 256>>>(n2w1);
    kT1M<<<NBM, 256>>>(x, n2b1);                       // profile slot
    kCount<<<EE / 256, 256>>>(ei);
    kPackW<<<(20 * 4096 + 255) / 256, 256>>>(n2w1, n2w2, n1w1, n1w2);
    kScanA<<<NBLK, 1024>>>();
    kScanB<<<1, 32>>>();
    kScanC<<<NBLK, 1024>>>();
    kScatter<<<EE / 256, 256>>>(ei, ea);

    int xSel = 4;
    const float* xPtr = x;
    for (int l = 0; l < LLAY; l++) {
        const float* b2 = n2b2 + (size_t)l * HH;
        const float* c1 = n1b1 + (size_t)l * HH;
        const float* c2 = n1b2 + (size_t)l * HH;
        const float* b1n = (l + 1 < LLAY) ? n2b1 + (size_t)(l + 1) * HH : nullptr;
        int xNextSel = (l & 1) ? 3 : 2;

        kAggM<<<NN / 8, 256>>>(l);
        kNodeM<<<NBM, 256>>>(xSel, xPtr, xNextSel, b2, c1, c2, b1n, eps, bat, l);

        xSel = xNextSel;
        xPtr = nullptr;
    }

    kFinal<<<GG / 8, 320>>>(fw1, fb1, fw2, fb2, (float*)d_out);
}

// round 17
// speedup vs baseline: 1.1023x; 1.1023x over previous
#include <cuda_runtime.h>
#include <cuda_bf16.h>
#include <cstdint>

#define NN   50000
#define EE   800000
#define HH   64
#define EAD  16
#define LLAY 5
#define GG   512
#define IN2  80
#define FD   320   // L*H
#define NBLK 49    // ceil(NN/1024)
#define NBM  782   // ceil(NN/64)
#define SP   72    // smem k-stride (bf16) for 64-wide tiles
#define ECHK 128   // edges per kAggM chunk
#define EST  20    // bf16 k-stride for ea tiles
#define MWS  72    // float stride of mw rows

typedef unsigned long long ull;

// ---------------- device scratch ----------------
__device__ int   g_flag64;
__device__ int   g_cnt[NN];
__device__ int   g_off[NN + 1];
__device__ int   g_cur[NN];
__device__ int   g_bsum[NBLK];
__device__ int   g_srcS[EE];
// ea sorted by dst, bf16 hi/lo packed as mma fragment words; +128 edge pad for
// over-read by GEMM fragment loads on the final partial chunk
__device__ __align__(16) unsigned g_eaH[((size_t)EE + 128) * 8];
__device__ __align__(16) unsigned g_eaL[((size_t)EE + 128) * 8];
__device__ __align__(16) float g_t1[(size_t)NN * HH];
__device__ __align__(16) float g_agg[(size_t)NN * HH];
__device__ __align__(16) float g_xA[(size_t)NN * HH];
__device__ __align__(16) float g_xB[(size_t)NN * HH];
__device__ float g_pool[(size_t)GG * FD];
__device__ __align__(16) __nv_bfloat16 g_wB[20][2][64][SP];
__device__ __align__(16) __nv_bfloat16 g_wE[LLAY][2][64][EST];
__device__ __align__(16) __nv_bfloat16 g_wT[2][64][SP];

__device__ __forceinline__ int loadIdx(const void* p, long long i, int is64) {
    if (is64) return (int)((const long long*)p)[i];
    return ((const int*)p)[i];
}
__device__ __forceinline__ const float* pickIn(int sel, const float* xin) {
    switch (sel) { case 2: return g_xA; case 3: return g_xB; default: return xin; }
}
__device__ __forceinline__ float* pickOut(int sel) { return (sel == 2) ? g_xA : g_xB; }

// ---------------- bf16 pack helpers ----------------
__device__ __forceinline__ unsigned pbHi(float x, float y) {
    __nv_bfloat16 hx = __float2bfloat16(x), hy = __float2bfloat16(y);
    return (unsigned)__bfloat16_as_ushort(hx) | ((unsigned)__bfloat16_as_ushort(hy) << 16);
}
__device__ __forceinline__ unsigned pbLo(float x, float y) {
    __nv_bfloat16 hx = __float2bfloat16(x), hy = __float2bfloat16(y);
    float lx = x - __bfloat162float(hx), ly = y - __bfloat162float(hy);
    __nv_bfloat16 bx = __float2bfloat16(lx), by = __float2bfloat16(ly);
    return (unsigned)__bfloat16_as_ushort(bx) | ((unsigned)__bfloat16_as_ushort(by) << 16);
}

// ---------------- mma.sync m16n8k16 bf16 ----------------
__device__ __forceinline__ void mma16816(float* c, unsigned a0, unsigned a1,
                                         unsigned a2, unsigned a3,
                                         unsigned b0, unsigned b1) {
    asm volatile(
        "mma.sync.aligned.m16n8k16.row.col.f32.bf16.bf16.f32 "
        "{%0,%1,%2,%3}, {%4,%5,%6,%7}, {%8,%9}, {%0,%1,%2,%3};"
        : "+f"(c[0]), "+f"(c[1]), "+f"(c[2]), "+f"(c[3])
        : "r"(a0), "r"(a1), "r"(a2), "r"(a3), "r"(b0), "r"(b1));
}

// ---------------- setup ----------------
__global__ void kDetect(const void* ei) {
    const int* p = (const int*)ei;
    g_flag64 = (p[1] == 0 && p[3] == 0 && p[5] == 0 && p[7] == 0) ? 1 : 0;
}
__global__ void kZero() {
    int i = blockIdx.x * blockDim.x + threadIdx.x;
    if (i < NN) g_cnt[i] = 0;
    if (i < GG * FD) g_pool[i] = 0.f;
}
__global__ void kCount(const void* __restrict__ ei) {
    int e = blockIdx.x * blockDim.x + threadIdx.x;
    if (e >= EE) return;
    int f = g_flag64;
    int s = loadIdx(ei, e, f);
    int d = loadIdx(ei, (long long)EE + e, f);
    if (s != d) atomicAdd(&g_cnt[d], 1);
}
__global__ void kScanA() {
    __shared__ int wsum[32];
    int tid = threadIdx.x, lane = tid & 31, wid = tid >> 5;
    int i = blockIdx.x * 1024 + tid;
    int v = (i < NN) ? g_cnt[i] : 0;
    int x = v;
#pragma unroll
    for (int o = 1; o < 32; o <<= 1) {
        int t = __shfl_up_sync(0xffffffffu, x, o);
        if (lane >= o) x += t;
    }
    if (lane == 31) wsum[wid] = x;
    __syncthreads();
    if (tid < 32) {
        int y = wsum[tid];
#pragma unroll
        for (int o = 1; o < 32; o <<= 1) {
            int t = __shfl_up_sync(0xffffffffu, y, o);
            if (tid >= o) y += t;
        }
        wsum[tid] = y;
    }
    __syncthreads();
    int incl = x + (wid ? wsum[wid - 1] : 0);
    if (i < NN) g_off[i] = incl - v;
    if (tid == 1023) g_bsum[blockIdx.x] = incl;
}
__global__ void kScanB() {
    if (threadIdx.x == 0) {
        int s = 0;
        for (int b = 0; b < NBLK; b++) { int t = g_bsum[b]; g_bsum[b] = s; s += t; }
        g_off[NN] = s;
    }
}
__global__ void kScanC() {
    int i = blockIdx.x * 1024 + threadIdx.x;
    if (i < NN) {
        int v = g_off[i] + g_bsum[blockIdx.x];
        g_off[i] = v;
        g_cur[i] = v;
    }
}
// scatter: convert ea -> bf16 hi/lo fragment words ONCE, dst-sorted
__global__ void kScatter(const void* __restrict__ ei, const float* __restrict__ ea) {
    int e = blockIdx.x * blockDim.x + threadIdx.x;
    if (e >= EE) return;
    int f = g_flag64;
    int s = loadIdx(ei, e, f);
    int d = loadIdx(ei, (long long)EE + e, f);
    if (s == d) return;
    int pos = atomicAdd(&g_cur[d], 1);
    g_srcS[pos] = s;
    const float4* s4 = (const float4*)(ea + (size_t)e * EAD);
    uint4 h0, h1, l0, l1;
    {
        float4 v0 = s4[0], v1 = s4[1], v2 = s4[2], v3 = s4[3];
        h0.x = pbHi(v0.x, v0.y); h0.y = pbHi(v0.z, v0.w);
        h0.z = pbHi(v1.x, v1.y); h0.w = pbHi(v1.z, v1.w);
        h1.x = pbHi(v2.x, v2.y); h1.y = pbHi(v2.z, v2.w);
        h1.z = pbHi(v3.x, v3.y); h1.w = pbHi(v3.z, v3.w);
        l0.x = pbLo(v0.x, v0.y); l0.y = pbLo(v0.z, v0.w);
        l0.z = pbLo(v1.x, v1.y); l0.w = pbLo(v1.z, v1.w);
        l1.x = pbLo(v2.x, v2.y); l1.y = pbLo(v2.z, v2.w);
        l1.z = pbLo(v3.x, v3.y); l1.w = pbLo(v3.z, v3.w);
    }
    ((uint4*)g_eaH)[(size_t)pos * 2]     = h0;
    ((uint4*)g_eaH)[(size_t)pos * 2 + 1] = h1;
    ((uint4*)g_eaL)[(size_t)pos * 2]     = l0;
    ((uint4*)g_eaL)[(size_t)pos * 2 + 1] = l1;
}

// ---------------- weight packing ----------------
__global__ void kPackW(const float* __restrict__ n2w1, const float* __restrict__ n2w2,
                       const float* __restrict__ n1w1, const float* __restrict__ n1w2) {
    int idx = blockIdx.x * 256 + threadIdx.x;
    if (idx >= 20 * 4096) return;
    int m = idx / 4096;
    int e = idx % 4096;
    int k = e >> 6, c = e & 63;
    int l = m >> 2, s = m & 3;
    float v;
    if (s == 0)      v = n2w2[((size_t)l * 64 + k) * 64 + c];
    else if (s == 1) v = n1w1[((size_t)l * 64 + k) * 64 + c];
    else if (s == 2) v = n1w2[((size_t)l * 64 + k) * 64 + c];
    else             v = (l < 4) ? n2w1[((size_t)(l + 1) * 80 + k) * 64 + c] : 0.f;
    __nv_bfloat16 hi = __float2bfloat16(v);
    __nv_bfloat16 lo = __float2bfloat16(v - __bfloat162float(hi));
    g_wB[m][0][c][k] = hi;
    g_wB[m][1][c][k] = lo;
}
__global__ void kPackE(const float* __restrict__ n2w1) {
    int idx = blockIdx.x * 256 + threadIdx.x;
    if (idx < LLAY * 1024) {
        int l = idx >> 10, e = idx & 1023;
        int k = e >> 6, c = e & 63;
        float v = n2w1[((size_t)l * IN2 + 64 + k) * HH + c];
        __nv_bfloat16 hi = __float2bfloat16(v);
        __nv_bfloat16 lo = __float2bfloat16(v - __bfloat162float(hi));
        g_wE[l][0][c][k] = hi;
        g_wE[l][1][c][k] = lo;
    } else if (idx < LLAY * 1024 + 4096) {
        int e = idx - LLAY * 1024;
        int k = e >> 6, c = e & 63;
        float v = n2w1[(size_t)k * HH + c];
        __nv_bfloat16 hi = __float2bfloat16(v);
        __nv_bfloat16 lo = __float2bfloat16(v - __bfloat162float(hi));
        g_wT[0][c][k] = hi;
        g_wT[1][c][k] = lo;
    }
}

// ---------------- kT1M: t1 = x @ W1a(l0) + b1, 256 threads / 8 warps ----------------
__global__ __launch_bounds__(256) void kT1M(const float* __restrict__ X,
                                            const float* __restrict__ B) {
    __shared__ __align__(16) __nv_bfloat16 sAhi[64][SP];
    __shared__ __align__(16) __nv_bfloat16 sAlo[64][SP];
    __shared__ __align__(16) __nv_bfloat16 sWhi[64][SP];
    __shared__ __align__(16) __nv_bfloat16 sWlo[64][SP];
    __shared__ float sB[64];
    int tid = threadIdx.x, lane = tid & 31, warp = tid >> 5;
    int g8 = lane >> 2, tg = lane & 3;
    int eg = warp >> 1, nh = warp & 1;
    int base = blockIdx.x * 64;
    if (tid < 64) sB[tid] = B[tid];
    for (int i = tid; i < 1024; i += 256) {
        int r = i >> 4, cc = (i & 15) << 2;
        int gr = base + r;
        float4 v = (gr < NN) ? *(const float4*)&X[(size_t)gr * HH + cc]
                             : make_float4(0.f, 0.f, 0.f, 0.f);
        *(unsigned*)&sAhi[r][cc]     = pbHi(v.x, v.y);
        *(unsigned*)&sAhi[r][cc + 2] = pbHi(v.z, v.w);
        *(unsigned*)&sAlo[r][cc]     = pbLo(v.x, v.y);
        *(unsigned*)&sAlo[r][cc + 2] = pbLo(v.z, v.w);
    }
    {
        const float4* sH = (const float4*)&g_wT[0][0][0];
        const float4* sL = (const float4*)&g_wT[1][0][0];
        float4* dH = (float4*)&sWhi[0][0];
        float4* dL = (float4*)&sWlo[0][0];
        for (int i = tid; i < 576; i += 256) { dH[i] = sH[i]; dL[i] = sL[i]; }
    }
    __syncthreads();
    int lr0 = eg * 16 + g8, lr1 = lr0 + 8;
    float acc[4][4];
#pragma unroll
    for (int nt = 0; nt < 4; nt++)
#pragma unroll
        for (int j = 0; j < 4; j++) acc[nt][j] = 0.f;
#pragma unroll
    for (int k = 0; k < 4; k++) {
        int k0 = k * 16 + tg * 2;
        unsigned ah0 = *(const unsigned*)&sAhi[lr0][k0];
        unsigned ah1 = *(const unsigned*)&sAhi[lr1][k0];
        unsigned ah2 = *(const unsigned*)&sAhi[lr0][k0 + 8];
        unsigned ah3 = *(const unsigned*)&sAhi[lr1][k0 + 8];
        unsigned al0 = *(const unsigned*)&sAlo[lr0][k0];
        unsigned al1 = *(const unsigned*)&sAlo[lr1][k0];
        unsigned al2 = *(const unsigned*)&sAlo[lr0][k0 + 8];
        unsigned al3 = *(const unsigned*)&sAlo[lr1][k0 + 8];
#pragma unroll
        for (int nt = 0; nt < 4; nt++) {
            int nr = nh * 32 + nt * 8 + g8;
            unsigned bh0 = *(const unsigned*)&sWhi[nr][k0];
            unsigned bh1 = *(const unsigned*)&sWhi[nr][k0 + 8];
            unsigned bl0 = *(const unsigned*)&sWlo[nr][k0];
            unsigned bl1 = *(const unsigned*)&sWlo[nr][k0 + 8];
            mma16816(acc[nt], ah0, ah1, ah2, ah3, bh0, bh1);
            mma16816(acc[nt], ah0, ah1, ah2, ah3, bl0, bl1);
            mma16816(acc[nt], al0, al1, al2, al3, bh0, bh1);
        }
    }
    int r0 = base + lr0, r1 = base + lr1;
#pragma unroll
    for (int nt = 0; nt < 4; nt++) {
        int col0 = nh * 32 + nt * 8 + tg * 2;
        if (r0 < NN)
            *(float2*)&g_t1[(size_t)r0 * HH + col0] =
                make_float2(acc[nt][0] + sB[col0], acc[nt][1] + sB[col0 + 1]);
        if (r1 < NN)
            *(float2*)&g_t1[(size_t)r1 * HH + col0] =
                make_float2(acc[nt][2] + sB[col0], acc[nt][3] + sB[col0 + 1]);
    }
}

// ---------------- kAggM: GEMM fragments direct from global, 2 barriers/chunk ----------------
__global__ __launch_bounds__(256) void kAggM(int layer) {
    __shared__ __align__(16) float mw[ECHK][MWS];        // 36864B
    __shared__ __align__(16) __nv_bfloat16 sWh[64][EST];
    __shared__ __align__(16) __nv_bfloat16 sWl[64][EST];
    __shared__ int ssrc[ECHK];

    int tid = threadIdx.x, lane = tid & 31, warp = tid >> 5;
    int g8 = lane >> 2, tg = lane & 3;

    for (int i = tid; i < 1024; i += 256) {
        int c = i >> 4, k = i & 15;
        sWh[c][k] = g_wE[layer][0][c][k];
        sWl[c][k] = g_wE[layer][1][c][k];
    }

    int nb = blockIdx.x * 8;
    int n = nb + warp;
    int beg = g_off[n], end = g_off[n + 1];
    int bBeg = g_off[nb], bEnd = g_off[nb + 8];
    float accA = 0.f, accB = 0.f;

    for (int cb = bBeg; cb < bEnd; cb += ECHK) {
        int cnt = min(ECHK, bEnd - cb);
        __syncthreads();                 // prev epilogue done with mw & ssrc; weights ready
        for (int i = tid; i < cnt; i += 256) ssrc[i] = g_srcS[cb + i];

        // GEMM: A-fragments loaded straight from pre-packed global ea
        float d[8][4];
#pragma unroll
        for (int nt = 0; nt < 8; nt++)
#pragma unroll
            for (int j = 0; j < 4; j++) d[nt][j] = 0.f;
        {
            int er0 = warp * 16 + g8;
            size_t rowA = (size_t)(cb + er0) * 8;
            size_t rowB = (size_t)(cb + er0 + 8) * 8;
            unsigned ah0 = g_eaH[rowA + tg];
            unsigned ah1 = g_eaH[rowB + tg];
            unsigned ah2 = g_eaH[rowA + tg + 4];
            unsigned ah3 = g_eaH[rowB + tg + 4];
            unsigned al0 = g_eaL[rowA + tg];
            unsigned al1 = g_eaL[rowB + tg];
            unsigned al2 = g_eaL[rowA + tg + 4];
            unsigned al3 = g_eaL[rowB + tg + 4];
            int k0 = tg * 2;
#pragma unroll
            for (int nt = 0; nt < 8; nt++) {
                int nr = nt * 8 + g8;
                unsigned bh0 = *(const unsigned*)&sWh[nr][k0];
                unsigned bh1 = *(const unsigned*)&sWh[nr][k0 + 8];
                unsigned bl0 = *(const unsigned*)&sWl[nr][k0];
                unsigned bl1 = *(const unsigned*)&sWl[nr][k0 + 8];
                mma16816(d[nt], ah0, ah1, ah2, ah3, bh0, bh1);
                mma16816(d[nt], ah0, ah1, ah2, ah3, bl0, bl1);
                mma16816(d[nt], al0, al1, al2, al3, bh0, bh1);
            }
        }
        // store mw fragments (mw free since top-of-loop barrier)
        {
            int er0 = warp * 16 + g8;
#pragma unroll
            for (int nt = 0; nt < 8; nt++) {
                int c0 = nt * 8 + tg * 2;
                *(float2*)&mw[er0][c0]     = make_float2(d[nt][0], d[nt][1]);
                *(float2*)&mw[er0 + 8][c0] = make_float2(d[nt][2], d[nt][3]);
            }
        }
        __syncthreads();                 // mw + ssrc visible

        int myB = max(beg, cb), myE = min(end, cb + cnt);
        int m = myE - myB;
        if (m > 0) {
            int q0 = myB - cb;
            float ga0, gb0, ga1 = 0.f, gb1 = 0.f, ga2 = 0.f, gb2 = 0.f;
            { int s = ssrc[q0];
              ga0 = g_t1[(size_t)s * HH + lane]; gb0 = g_t1[(size_t)s * HH + lane + 32]; }
            if (m > 1) { int s = ssrc[q0 + 1];
              ga1 = g_t1[(size_t)s * HH + lane]; gb1 = g_t1[(size_t)s * HH + lane + 32]; }
            if (m > 2) { int s = ssrc[q0 + 2];
              ga2 = g_t1[(size_t)s * HH + lane]; gb2 = g_t1[(size_t)s * HH + lane + 32]; }
            for (int q = 0; q < m; q++) {
                float nga = 0.f, ngb = 0.f;
                if (q + 3 < m) {
                    int s = ssrc[q0 + q + 3];
                    nga = g_t1[(size_t)s * HH + lane];
                    ngb = g_t1[(size_t)s * HH + lane + 32];
                }
                float m0 = mw[q0 + q][lane];
                float m1 = mw[q0 + q][lane + 32];
                accA += fmaxf(ga0 + m0, 0.f);
                accB += fmaxf(gb0 + m1, 0.f);
                ga0 = ga1; gb0 = gb1; ga1 = ga2; gb1 = gb2; ga2 = nga; gb2 = ngb;
            }
        }
    }
    g_agg[(size_t)n * HH + lane] = accA;
    g_agg[(size_t)n * HH + lane + 32] = accB;
}

// ---------------- kNodeM: fused node update, 256 threads / 8 warps ----------------
__global__ __launch_bounds__(256) void kNodeM(int xSel, const float* __restrict__ xExt,
                                              int xOutSel,
                                              const float* __restrict__ b2,
                                              const float* __restrict__ c1,
                                              const float* __restrict__ c2,
                                              const float* __restrict__ b1n,
                                              const float* __restrict__ epsPtr,
                                              const void* __restrict__ batch, int layer) {
    __shared__ __align__(16) __nv_bfloat16 sAhi[64][SP];
    __shared__ __align__(16) __nv_bfloat16 sAlo[64][SP];
    __shared__ __align__(16) __nv_bfloat16 sWhi[64][SP];
    __shared__ __align__(16) __nv_bfloat16 sWlo[64][SP];
    __shared__ float sBias[4][64];

    int tid = threadIdx.x, lane = tid & 31, warp = tid >> 5;
    int g8 = lane >> 2, tg = lane & 3;
    int eg = warp >> 1, nh = warp & 1;
    int base = blockIdx.x * 64;
    const float* X = pickIn(xSel, xExt);
    float* Xo = pickOut(xOutSel);
    int nStages = (layer < LLAY - 1) ? 4 : 3;
    bool writeX = (layer < LLAY - 1);
    int f64 = g_flag64;

    if (tid < 64) {
        sBias[0][tid] = b2[tid];
        sBias[1][tid] = c1[tid];
        sBias[2][tid] = c2[tid];
        sBias[3][tid] = b1n ? b1n[tid] : 0.f;
    }
    for (int i = tid; i < 1024; i += 256) {
        int r = i >> 4, cc = (i & 15) << 2;
        int gr = base + r;
        float4 v = (gr < NN) ? *(const float4*)&g_agg[(size_t)gr * HH + cc]
                             : make_float4(0.f, 0.f, 0.f, 0.f);
        *(unsigned*)&sAhi[r][cc]     = pbHi(v.x, v.y);
        *(unsigned*)&sAhi[r][cc + 2] = pbHi(v.z, v.w);
        *(unsigned*)&sAlo[r][cc]     = pbLo(v.x, v.y);
        *(unsigned*)&sAlo[r][cc + 2] = pbLo(v.z, v.w);
    }
    {
        const float4* sH = (const float4*)&g_wB[layer * 4][0][0][0];
        const float4* sL = (const float4*)&g_wB[layer * 4][1][0][0];
        float4* dH = (float4*)&sWhi[0][0];
        float4* dL = (float4*)&sWlo[0][0];
        for (int i = tid; i < 576; i += 256) { dH[i] = sH[i]; dL[i] = sL[i]; }
    }

    int lr0 = eg * 16 + g8, lr1 = lr0 + 8;
    int r0 = base + lr0, r1 = base + lr1;
    bool valid0 = r0 < NN, valid1 = r1 < NN;
    float ope = 1.f + epsPtr[0];
    float cnt0 = valid0 ? (float)g_cnt[r0] : 0.f;
    float cnt1 = valid1 ? (float)g_cnt[r1] : 0.f;
    int gb0 = valid0 ? loadIdx(batch, r0, f64) : 0;
    int gb1 = valid1 ? loadIdx(batch, r1, f64) : 0;

    for (int s = 0; s < nStages; s++) {
        __syncthreads();
        float acc[4][4];
#pragma unroll
        for (int nt = 0; nt < 4; nt++)
#pragma unroll
            for (int j = 0; j < 4; j++) acc[nt][j] = 0.f;

#pragma unroll
        for (int k = 0; k < 4; k++) {
            int k0 = k * 16 + tg * 2;
            unsigned ah0 = *(const unsigned*)&sAhi[lr0][k0];
            unsigned ah1 = *(const unsigned*)&sAhi[lr1][k0];
            unsigned ah2 = *(const unsigned*)&sAhi[lr0][k0 + 8];
            unsigned ah3 = *(const unsigned*)&sAhi[lr1][k0 + 8];
            unsigned al0 = *(const unsigned*)&sAlo[lr0][k0];
            unsigned al1 = *(const unsigned*)&sAlo[lr1][k0];
            unsigned al2 = *(const unsigned*)&sAlo[lr0][k0 + 8];
            unsigned al3 = *(const unsigned*)&sAlo[lr1][k0 + 8];
#pragma unroll
            for (int nt = 0; nt < 4; nt++) {
                int nr = nh * 32 + nt * 8 + g8;
                unsigned bh0 = *(const unsigned*)&sWhi[nr][k0];
                unsigned bh1 = *(const unsigned*)&sWhi[nr][k0 + 8];
                unsigned bl0 = *(const unsigned*)&sWlo[nr][k0];
                unsigned bl1 = *(const unsigned*)&sWlo[nr][k0 + 8];
                mma16816(acc[nt], ah0, ah1, ah2, ah3, bh0, bh1);
                mma16816(acc[nt], ah0, ah1, ah2, ah3, bl0, bl1);
                mma16816(acc[nt], al0, al1, al2, al3, bh0, bh1);
            }
        }
        __syncthreads();

        if (s + 1 < nStages) {
            const float4* sH = (const float4*)&g_wB[layer * 4 + s + 1][0][0][0];
            const float4* sL = (const float4*)&g_wB[layer * 4 + s + 1][1][0][0];
            float4* dH = (float4*)&sWhi[0][0];
            float4* dL = (float4*)&sWlo[0][0];
            for (int i = tid; i < 576; i += 256) { dH[i] = sH[i]; dL[i] = sL[i]; }
        }

        bool last = (s == nStages - 1);
#pragma unroll
        for (int nt = 0; nt < 4; nt++) {
            int col0 = nh * 32 + nt * 8 + tg * 2;
            float v00, v01, v10, v11;
            if (s == 0) {
                float2 x0 = valid0 ? *(const float2*)&X[(size_t)r0 * HH + col0]
                                   : make_float2(0.f, 0.f);
                float2 x1 = valid1 ? *(const float2*)&X[(size_t)r1 * HH + col0]
                                   : make_float2(0.f, 0.f);
                v00 = acc[nt][0] + ope * x0.x + cnt0 * sBias[0][col0];
                v01 = acc[nt][1] + ope * x0.y + cnt0 * sBias[0][col0 + 1];
                v10 = acc[nt][2] + ope * x1.x + cnt1 * sBias[0][col0];
                v11 = acc[nt][3] + ope * x1.y + cnt1 * sBias[0][col0 + 1];
            } else if (s == 1) {
                v00 = fmaxf(acc[nt][0] + sBias[1][col0], 0.f);
                v01 = fmaxf(acc[nt][1] + sBias[1][col0 + 1], 0.f);
                v10 = fmaxf(acc[nt][2] + sBias[1][col0], 0.f);
                v11 = fmaxf(acc[nt][3] + sBias[1][col0 + 1], 0.f);
            } else if (s == 2) {
                v00 = acc[nt][0] + sBias[2][col0];
                v01 = acc[nt][1] + sBias[2][col0 + 1];
                v10 = acc[nt][2] + sBias[2][col0];
                v11 = acc[nt][3] + sBias[2][col0 + 1];
                if (valid0) {
                    if (writeX) *(float2*)&Xo[(size_t)r0 * HH + col0] = make_float2(v00, v01);
                    atomicAdd(&g_pool[(size_t)gb0 * FD + layer * HH + col0], v00);
                    atomicAdd(&g_pool[(size_t)gb0 * FD + layer * HH + col0 + 1], v01);
                }
                if (valid1) {
                    if (writeX) *(float2*)&Xo[(size_t)r1 * HH + col0] = make_float2(v10, v11);
                    atomicAdd(&g_pool[(size_t)gb1 * FD + layer * HH + col0], v10);
                    atomicAdd(&g_pool[(size_t)gb1 * FD + layer * HH + col0 + 1], v11);
                }
            } else {
                v00 = acc[nt][0] + sBias[3][col0];
                v01 = acc[nt][1] + sBias[3][col0 + 1];
                v10 = acc[nt][2] + sBias[3][col0];
                v11 = acc[nt][3] + sBias[3][col0 + 1];
                if (valid0) *(float2*)&g_t1[(size_t)r0 * HH + col0] = make_float2(v00, v01);
                if (valid1) *(float2*)&g_t1[(size_t)r1 * HH + col0] = make_float2(v10, v11);
            }
            if (!last) {
                *(unsigned*)&sAhi[lr0][col0] = pbHi(v00, v01);
                *(unsigned*)&sAlo[lr0][col0] = pbLo(v00, v01);
                *(unsigned*)&sAhi[lr1][col0] = pbHi(v10, v11);
                *(unsigned*)&sAlo[lr1][col0] = pbLo(v10, v11);
            }
        }
    }
}

// ---------------- final MLP ----------------
__global__ __launch_bounds__(320) void kFinal(const float* __restrict__ fw1,
                                              const float* __restrict__ fb1,
                                              const float* __restrict__ fw2,
                                              const float* __restrict__ fb2,
                                              float* __restrict__ out) {
    __shared__ float fsh[8][FD];
    __shared__ float hsh[8][FD];
    int tid = threadIdx.x;
    int gbase = blockIdx.x * 8;
    for (int i = tid; i < 8 * FD; i += 320) {
        int gg = i / FD, k = i % FD;
        fsh[gg][k] = g_pool[(size_t)(gbase + gg) * FD + k];
    }
    __syncthreads();
    float acc[8] = {0, 0, 0, 0, 0, 0, 0, 0};
    for (int k = 0; k < FD; k++) {
        float w = fw1[(size_t)k * FD + tid];
#pragma unroll
        for (int gg = 0; gg < 8; gg++) acc[gg] = fmaf(fsh[gg][k], w, acc[gg]);
    }
    float b = fb1[tid];
#pragma unroll
    for (int gg = 0; gg < 8; gg++) hsh[gg][tid] = fmaxf(acc[gg] + b, 0.f);
    __syncthreads();
    int warp = tid >> 5, lane = tid & 31;
    if (warp < 8) {
        float s = 0.f;
        for (int k = lane; k < FD; k += 32) s += hsh[warp][k] * fw2[k];
#pragma unroll
        for (int o = 16; o; o >>= 1) s += __shfl_down_sync(0xffffffffu, s, o);
        if (lane == 0) out[gbase + warp] = s + fb2[0];
    }
}

// ---------------- launch ----------------
extern "C" void kernel_launch(void* const* d_in, const int* in_sizes, int n_in,
                              void* d_out, int out_size) {
    const float* x    = (const float*)d_in[0];
    const void*  ei   = d_in[1];
    const float* ea   = (const float*)d_in[2];
    const void*  bat  = d_in[3];
    const float* n2w1 = (const float*)d_in[4];
    const float* n2b1 = (const float*)d_in[5];
    const float* n2w2 = (const float*)d_in[6];
    const float* n2b2 = (const float*)d_in[7];
    const float* n1w1 = (const float*)d_in[8];
    const float* n1b1 = (const float*)d_in[9];
    const float* n1w2 = (const float*)d_in[10];
    const float* n1b2 = (const float*)d_in[11];
    const float* fw1  = (const float*)d_in[12];
    const float* fb1  = (const float*)d_in[13];
    const float* fw2  = (const float*)d_in[14];
    const float* fb2  = (const float*)d_in[15];
    const float* eps  = (const float*)d_in[16];

    kDetect<<<1, 1>>>(ei);
    kZero<<<(GG * FD + 255) / 256, 256>>>();
    kPackE<<<(LLAY * 1024 + 4096 + 255) / 256, 256>>>(n2w1);
    kT1M<<<NBM, 256>>>(x, n2b1);                       // profile slot
    kCount<<<EE / 256, 256>>>(ei);
    kPackW<<<(20 * 4096 + 255) / 256, 256>>>(n2w1, n2w2, n1w1, n1w2);
    kScanA<<<NBLK, 1024>>>();
    kScanB<<<1, 32>>>();
    kScanC<<<NBLK, 1024>>>();
    kScatter<<<EE / 256, 256>>>(ei, ea);

    int xSel = 4;
    const float* xPtr = x;
    for (int l = 0; l < LLAY; l++) {
        const float* b2 = n2b2 + (size_t)l * HH;
        const float* c1 = n1b1 + (size_t)l * HH;
        const float* c2 = n1b2 + (size_t)l * HH;
        const float* b1n = (l + 1 < LLAY) ? n2b1 + (size_t)(l + 1) * HH : nullptr;
        int xNextSel = (l & 1) ? 3 : 2;

        kAggM<<<NN / 8, 256>>>(l);
        kNodeM<<<NBM, 256>>>(xSel, xPtr, xNextSel, b2, c1, c2, b1n, eps, bat, l);

        xSel = xNextSel;
        xPtr = nullptr;
    }

    kFinal<<<GG / 8, 320>>>(fw1, fb1, fw2, fb2, (float*)d_out);
}